// round 1
// baseline (speedup 1.0000x reference)
#include <cuda_runtime.h>
#include <cuda_bf16.h>
#include <math.h>

// Problem constants (fixed shapes)
#define NN      4096      // nodes
#define KIN     1433      // in features
#define NH      8         // heads
#define DHD     8         // per-head dim
#define FOUT    64        // NH*DHD
#define LRELU   0.2f

// Attention tiling
#define TI      128       // i rows per block
#define TJ      64        // j tile in smem
#define RPT     4         // rows per thread (TI / 32 groups)
#define SPLITS  8         // j-axis splits
#define CHUNK   (NN / SPLITS)   // 512

// ---------------- scratch (no allocations allowed) ----------------
__device__ __align__(16) float g_buf[NN * FOUT];            // 1 MB
__device__ __align__(16) float4 Lbuf[NN * NH];              // sl, e^sl, e^{0.2 sl}
__device__ __align__(16) float4 Rbuf[NN * NH];              // sr, e^sr, e^{0.2 sr}
__device__ __align__(16) float pacc_buf[SPLITS * NN * FOUT];// 8 MB partial acc
__device__ __align__(16) float psum_buf[SPLITS * NN * NH];  // 1 MB partial denom

// ---------------- Kernel 1: g = vert @ W  (fp32 tiled GEMM) ----------------
// A: [NN][KIN], B: [KIN][64], C: [NN][64]. Block: 32 rows x 64 cols, 256 thr.
__global__ void __launch_bounds__(256) gemm_proj(const float* __restrict__ A,
                                                 const float* __restrict__ B)
{
    __shared__ float As[16][36];   // As[k][m], padded
    __shared__ float Bs[16][64];
    const int tid = threadIdx.x;
    const int m0  = blockIdx.x * 32;
    const int tx  = tid & 15;      // col group -> cols tx*4..+4
    const int ty  = tid >> 4;      // row group -> rows ty*2..+2

    float acc[2][4] = {};

    for (int k0 = 0; k0 < KIN; k0 += 16) {
        // A tile: 32 m x 16 k (2 elems / thread)
        {
            const int k = tid & 15;
            const int r = tid >> 4;
            #pragma unroll
            for (int it = 0; it < 2; it++) {
                const int row = r + it * 16;
                float v = 0.f;
                if (k0 + k < KIN) v = A[(size_t)(m0 + row) * KIN + k0 + k];
                As[k][row] = v;
            }
        }
        // B tile: 16 k x 64 n (4 elems / thread)
        {
            const int c  = tid & 63;
            const int rb = tid >> 6;
            #pragma unroll
            for (int it = 0; it < 4; it++) {
                const int rr = rb + it * 4;
                float v = 0.f;
                if (k0 + rr < KIN) v = B[(size_t)(k0 + rr) * 64 + c];
                Bs[rr][c] = v;
            }
        }
        __syncthreads();

        #pragma unroll
        for (int kk = 0; kk < 16; kk++) {
            const float a0 = As[kk][ty * 2 + 0];
            const float a1 = As[kk][ty * 2 + 1];
            const float4 b = *(const float4*)&Bs[kk][tx * 4];
            acc[0][0] += a0 * b.x; acc[0][1] += a0 * b.y;
            acc[0][2] += a0 * b.z; acc[0][3] += a0 * b.w;
            acc[1][0] += a1 * b.x; acc[1][1] += a1 * b.y;
            acc[1][2] += a1 * b.z; acc[1][3] += a1 * b.w;
        }
        __syncthreads();
    }

    #pragma unroll
    for (int i = 0; i < 2; i++) {
        float4 v = make_float4(acc[i][0], acc[i][1], acc[i][2], acc[i][3]);
        *(float4*)&g_buf[(size_t)(m0 + ty * 2 + i) * 64 + tx * 4] = v;
    }
}

// ---------------- Kernel 2: per-(node,head) scores + factored exps ----------------
__global__ void __launch_bounds__(256) prep_scores(const float* __restrict__ a_l,
                                                   const float* __restrict__ a_r)
{
    const int t = blockIdx.x * blockDim.x + threadIdx.x;
    if (t >= NN * NH) return;
    const int n = t >> 3;
    const int h = t & 7;

    const float4 g0 = *(const float4*)&g_buf[(size_t)n * 64 + h * 8 + 0];
    const float4 g1 = *(const float4*)&g_buf[(size_t)n * 64 + h * 8 + 4];
    const float4 al0 = *(const float4*)&a_l[h * 8 + 0];
    const float4 al1 = *(const float4*)&a_l[h * 8 + 4];
    const float4 ar0 = *(const float4*)&a_r[h * 8 + 0];
    const float4 ar1 = *(const float4*)&a_r[h * 8 + 4];

    const float sl = g0.x*al0.x + g0.y*al0.y + g0.z*al0.z + g0.w*al0.w
                   + g1.x*al1.x + g1.y*al1.y + g1.z*al1.z + g1.w*al1.w;
    const float sr = g0.x*ar0.x + g0.y*ar0.y + g0.z*ar0.z + g0.w*ar0.w
                   + g1.x*ar1.x + g1.y*ar1.y + g1.z*ar1.z + g1.w*ar1.w;

    Lbuf[t] = make_float4(sl, expf(sl), expf(LRELU * sl), 0.f);
    Rbuf[t] = make_float4(sr, expf(sr), expf(LRELU * sr), 0.f);
}

// ---------------- Kernel 3: masked softmax-aggregation (exp-free inner loop) ----------------
// Grid: (SPLITS, NN/TI). 256 threads: h = tid&7, grp = tid>>3, each thread owns
// RPT=4 consecutive rows of the TI-row tile for head h.
__global__ void __launch_bounds__(256) attn_kernel(const int* __restrict__ edge)
{
    __shared__ float gs[TJ * 64];                 // 16 KB: g tile
    __shared__ float4 rs[TJ * 8];                 // 8 KB: (sr, e^sr, e^.2sr) per (j,h)
    __shared__ unsigned char es[TJ][TI + 4];      // 8.4 KB: edge tile, transposed [j][i]

    const int tid = threadIdx.x;
    const int h   = tid & 7;
    const int grp = tid >> 3;                     // 0..31
    const int split = blockIdx.x;
    const int i0  = blockIdx.y * TI;
    const int j0  = split * CHUNK;

    float sl[RPT], elp[RPT], eln[RPT], ssum[RPT];
    float acc[RPT][8];
    #pragma unroll
    for (int r = 0; r < RPT; r++) {
        const int irow = i0 + grp * RPT + r;
        const float4 L = Lbuf[(size_t)irow * 8 + h];
        sl[r] = L.x; elp[r] = L.y; eln[r] = L.z;
        ssum[r] = 0.f;
        #pragma unroll
        for (int d = 0; d < 8; d++) acc[r][d] = 0.f;
    }

    const float4* g4 = (const float4*)g_buf;
    const int4*   e4 = (const int4*)edge;

    for (int jt = 0; jt < CHUNK; jt += TJ) {
        const int jb = j0 + jt;

        // g tile: TJ*16 float4 = 1024 -> 4 per thread
        #pragma unroll
        for (int k = 0; k < (TJ * 16) / 256; k++) {
            const int idx = tid + k * 256;
            ((float4*)gs)[idx] = g4[(size_t)jb * 16 + idx];
        }
        // r tile: TJ*8 float4 = 512 -> 2 per thread
        #pragma unroll
        for (int k = 0; k < (TJ * 8) / 256; k++) {
            const int idx = tid + k * 256;
            rs[idx] = Rbuf[(size_t)jb * 8 + idx];
        }
        // edge tile: TI x TJ ints = 2048 int4 -> 8 per thread; store transposed bytes
        #pragma unroll
        for (int k = 0; k < (TI * TJ / 4) / 256; k++) {
            const int idx = tid + k * 256;          // int4 index in tile
            const int ii  = idx / (TJ / 4);         // TJ/4 = 16 int4 per row
            const int jq  = idx % (TJ / 4);
            const int4 v  = e4[(size_t)(i0 + ii) * (NN / 4) + (jb >> 2) + jq];
            const int j   = jq * 4;
            es[j + 0][ii] = (unsigned char)(v.x != 0);
            es[j + 1][ii] = (unsigned char)(v.y != 0);
            es[j + 2][ii] = (unsigned char)(v.z != 0);
            es[j + 3][ii] = (unsigned char)(v.w != 0);
        }
        __syncthreads();

        for (int j = 0; j < TJ; j++) {
            const float4 rv = rs[j * 8 + h];
            const float4 ga = ((const float4*)gs)[j * 16 + h * 2 + 0];
            const float4 gb = ((const float4*)gs)[j * 16 + h * 2 + 1];
            const unsigned int mu = *(const unsigned int*)&es[j][grp * 4];
            #pragma unroll
            for (int r = 0; r < RPT; r++) {
                const float x  = sl[r] + rv.x;
                const bool pos = (x >= 0.f);
                const float wl = pos ? elp[r] : eln[r];
                const float wr = pos ? rv.y : rv.z;
                float w = wl * wr;
                if (((mu >> (r * 8)) & 0xffu) == 0u) w = 0.f;
                ssum[r]   += w;
                acc[r][0] += w * ga.x; acc[r][1] += w * ga.y;
                acc[r][2] += w * ga.z; acc[r][3] += w * ga.w;
                acc[r][4] += w * gb.x; acc[r][5] += w * gb.y;
                acc[r][6] += w * gb.z; acc[r][7] += w * gb.w;
            }
        }
        __syncthreads();
    }

    // write partials
    #pragma unroll
    for (int r = 0; r < RPT; r++) {
        const int irow = i0 + grp * RPT + r;
        float* pa = &pacc_buf[((size_t)split * NN + irow) * 64 + h * 8];
        *(float4*)(pa + 0) = make_float4(acc[r][0], acc[r][1], acc[r][2], acc[r][3]);
        *(float4*)(pa + 4) = make_float4(acc[r][4], acc[r][5], acc[r][6], acc[r][7]);
        psum_buf[((size_t)split * NN + irow) * 8 + h] = ssum[r];
    }
}

// ---------------- Kernel 4: combine splits, normalize, ELU ----------------
__global__ void __launch_bounds__(256) combine_kernel(float* __restrict__ out)
{
    const int t = blockIdx.x * blockDim.x + threadIdx.x;   // 0 .. NN*64-1
    if (t >= NN * FOUT) return;
    const int i = t >> 6;
    const int c = t & 63;
    const int h = c >> 3;

    float a = 0.f, den = 0.f;
    #pragma unroll
    for (int s = 0; s < SPLITS; s++) {
        a   += pacc_buf[((size_t)s * NN + i) * 64 + c];
        den += psum_buf[((size_t)s * NN + i) * 8 + h];
    }
    const float v = a / den;
    out[t] = (v >= 0.f) ? v : expm1f(v);
}

// ---------------- launch ----------------
extern "C" void kernel_launch(void* const* d_in, const int* in_sizes, int n_in,
                              void* d_out, int out_size)
{
    const float* vert = (const float*)d_in[0];   // [4096,1433]
    const int*   edge = (const int*)  d_in[1];   // [4096,4096]
    const float* W    = (const float*)d_in[2];   // [1433,64]
    const float* a_l  = (const float*)d_in[3];   // [8,8]
    const float* a_r  = (const float*)d_in[4];   // [8,8]
    float* out = (float*)d_out;                  // [4096,64]

    gemm_proj<<<NN / 32, 256>>>(vert, W);
    prep_scores<<<(NN * NH) / 256, 256>>>(a_l, a_r);
    attn_kernel<<<dim3(SPLITS, NN / TI), 256>>>(edge);
    combine_kernel<<<(NN * FOUT) / 256, 256>>>(out);
}